// round 10
// baseline (speedup 1.0000x reference)
#include <cuda_runtime.h>
#include <cuda_bf16.h>
#include <cstdint>

#define BB 8
#define CC 256
#define TT 2048
#define RR 32

// bf16 scratch
__device__ __nv_bfloat16 g_Qb[BB*TT*RR];    // [b][t][r]
__device__ __nv_bfloat16 g_Kb[BB*TT*RR];    // [b][t][r]
__device__ __nv_bfloat16 g_Vb[BB*CC*TT];    // [b][c][t]
__device__ __nv_bfloat16 g_Xb[BB*CC*TT];    // [b][c][t]
__device__ __nv_bfloat16 g_Wb[320*CC];      // [row][c]  rows: 0-31 q, 32-63 k, 64-319 v

// ---------------------------------------------------------------------------
// PTX helpers
// ---------------------------------------------------------------------------
__device__ __forceinline__ uint32_t smaddr(const void* p) {
    return (uint32_t)__cvta_generic_to_shared(p);
}
__device__ __forceinline__ void cp16(void* dst, const void* src) {
    asm volatile("cp.async.cg.shared.global [%0], [%1], 16;"
                 :: "r"(smaddr(dst)), "l"(src) : "memory");
}
__device__ __forceinline__ void cpcommit() {
    asm volatile("cp.async.commit_group;" ::: "memory");
}
__device__ __forceinline__ void cpwait0() {
    asm volatile("cp.async.wait_group 0;" ::: "memory");
}
__device__ __forceinline__ void ldsm4(uint32_t* r, const void* p) {
    asm volatile("ldmatrix.sync.aligned.m8n8.x4.shared.b16 {%0,%1,%2,%3}, [%4];"
        : "=r"(r[0]), "=r"(r[1]), "=r"(r[2]), "=r"(r[3])
        : "r"(smaddr(p)));
}
__device__ __forceinline__ void ldsm4t(uint32_t* r, const void* p) {
    asm volatile("ldmatrix.sync.aligned.m8n8.x4.trans.shared.b16 {%0,%1,%2,%3}, [%4];"
        : "=r"(r[0]), "=r"(r[1]), "=r"(r[2]), "=r"(r[3])
        : "r"(smaddr(p)));
}
__device__ __forceinline__ void mmabf(float* d, const uint32_t* a,
                                      uint32_t b0, uint32_t b1) {
    asm volatile(
        "mma.sync.aligned.m16n8k16.row.col.f32.bf16.bf16.f32 "
        "{%0,%1,%2,%3},{%4,%5,%6,%7},{%8,%9},{%0,%1,%2,%3};"
        : "+f"(d[0]), "+f"(d[1]), "+f"(d[2]), "+f"(d[3])
        : "r"(a[0]), "r"(a[1]), "r"(a[2]), "r"(a[3]), "r"(b0), "r"(b1));
}

// ---------------------------------------------------------------------------
// Prep kernels
// ---------------------------------------------------------------------------
__global__ __launch_bounds__(256) void cvt_x_kernel(const float* __restrict__ x) {
    size_t i = ((size_t)blockIdx.x*256 + threadIdx.x)*4;
    float4 v = *reinterpret_cast<const float4*>(&x[i]);
    __nv_bfloat162 h0 = __floats2bfloat162_rn(v.x, v.y);
    __nv_bfloat162 h1 = __floats2bfloat162_rn(v.z, v.w);
    uint2 pk;
    pk.x = *reinterpret_cast<uint32_t*>(&h0);
    pk.y = *reinterpret_cast<uint32_t*>(&h1);
    *reinterpret_cast<uint2*>(&g_Xb[i]) = pk;
}

__global__ __launch_bounds__(256) void cvt_w_kernel(
    const float* __restrict__ Wq, const float* __restrict__ Wk,
    const float* __restrict__ Wv) {
    int i = (blockIdx.x*256 + threadIdx.x)*4;
    int row = i >> 8, col = i & 255;
    const float* src = (row < 32) ? &Wq[row*CC + col]
                     : (row < 64) ? &Wk[(row-32)*CC + col]
                                  : &Wv[(row-64)*CC + col];
    float4 v = *reinterpret_cast<const float4*>(src);
    __nv_bfloat162 h0 = __floats2bfloat162_rn(v.x, v.y);
    __nv_bfloat162 h1 = __floats2bfloat162_rn(v.z, v.w);
    uint2 pk;
    pk.x = *reinterpret_cast<uint32_t*>(&h0);
    pk.y = *reinterpret_cast<uint32_t*>(&h1);
    *reinterpret_cast<uint2*>(&g_Wb[i]) = pk;
}

// ---------------------------------------------------------------------------
// Kernel 1: projections via bf16 mma (unchanged from round 5 — fast).
// ---------------------------------------------------------------------------
#define WST 72
#define XST 136
#define WBUF (64*WST)
#define XBUF (64*XST)
#define PROJ_SM_BYTES ((2*WBUF + 2*XBUF)*2)

__global__ __launch_bounds__(256, 2) void proj_kernel(
    const float* __restrict__ bq, const float* __restrict__ bk,
    const float* __restrict__ bv)
{
    extern __shared__ __align__(16) char smraw[];
    __nv_bfloat16* wbuf = (__nv_bfloat16*)smraw;     // [2][64][72]
    __nv_bfloat16* xbuf = wbuf + 2*WBUF;             // [2][64][136]

    const int b    = blockIdx.z;
    const int m0   = blockIdx.y * 64;
    const int n0   = blockIdx.x * 128;
    const int tid  = threadIdx.x;
    const int wid  = tid >> 5;
    const int lane = tid & 31;
    const int lq   = lane >> 2, lr = lane & 3;
    const int wm   = wid >> 1,  wn = wid & 1;
    const int l8   = (lane & 7) + ((lane & 8) ? 8 : 0);
    const int lc   = (lane >> 4) * 8;

    {
        #pragma unroll
        for (int j = 0; j < 2; j++) {
            int slot = tid + j*256;
            int row = slot >> 3, kc = (slot & 7)*8;
            cp16(&wbuf[row*WST + kc], &g_Wb[(m0+row)*CC + kc]);
        }
        #pragma unroll
        for (int j = 0; j < 4; j++) {
            int slot = tid + j*256;
            int row = slot >> 4, tc = (slot & 15)*8;
            cp16(&xbuf[row*XST + tc], &g_Xb[((size_t)b*CC + row)*TT + n0 + tc]);
        }
        cpcommit();
    }

    float acc[8][4];
    #pragma unroll
    for (int nf = 0; nf < 8; nf++)
        #pragma unroll
        for (int j = 0; j < 4; j++) acc[nf][j] = 0.f;

    for (int kc = 0; kc < 4; kc++) {
        const int buf = kc & 1;
        cpwait0();
        __syncthreads();

        if (kc + 1 < 4) {
            const int k0 = (kc+1)*64;
            __nv_bfloat16* wd = wbuf + (buf^1)*WBUF;
            __nv_bfloat16* xd = xbuf + (buf^1)*XBUF;
            #pragma unroll
            for (int j = 0; j < 2; j++) {
                int slot = tid + j*256;
                int row = slot >> 3, kcc = (slot & 7)*8;
                cp16(&wd[row*WST + kcc], &g_Wb[(m0+row)*CC + k0 + kcc]);
            }
            #pragma unroll
            for (int j = 0; j < 4; j++) {
                int slot = tid + j*256;
                int row = slot >> 4, tc = (slot & 15)*8;
                cp16(&xd[row*XST + tc], &g_Xb[((size_t)b*CC + k0 + row)*TT + n0 + tc]);
            }
            cpcommit();
        }

        const __nv_bfloat16* wb = wbuf + buf*WBUF;
        const __nv_bfloat16* xb = xbuf + buf*XBUF;
        #pragma unroll
        for (int ks = 0; ks < 4; ks++) {
            uint32_t a[4];
            ldsm4(a, &wb[(wm*16 + l8)*WST + ks*16 + lc]);
            #pragma unroll
            for (int ng = 0; ng < 4; ng++) {
                uint32_t bx[4];
                ldsm4t(bx, &xb[(ks*16 + l8)*XST + wn*64 + ng*16 + lc]);
                mmabf(acc[ng*2+0], a, bx[0], bx[1]);
                mmabf(acc[ng*2+1], a, bx[2], bx[3]);
            }
        }
        __syncthreads();
    }

    const int r0 = m0 + wm*16 + lq;
    const int r1 = r0 + 8;
    float bias0 = (r0 < 32) ? bq[r0] : (r0 < 64) ? bk[r0-32] : bv[r0-64];
    float bias1 = (r1 < 32) ? bq[r1] : (r1 < 64) ? bk[r1-32] : bv[r1-64];

    if (m0 >= 64) {
        int v0 = r0 - 64, v1 = r1 - 64;
        #pragma unroll
        for (int nf = 0; nf < 8; nf++) {
            int col = n0 + wn*64 + nf*8 + 2*lr;
            __nv_bfloat162 h0 = __floats2bfloat162_rn(acc[nf][0] + bias0,
                                                      acc[nf][1] + bias0);
            __nv_bfloat162 h1 = __floats2bfloat162_rn(acc[nf][2] + bias1,
                                                      acc[nf][3] + bias1);
            *reinterpret_cast<__nv_bfloat162*>(&g_Vb[((size_t)b*CC + v0)*TT + col]) = h0;
            *reinterpret_cast<__nv_bfloat162*>(&g_Vb[((size_t)b*CC + v1)*TT + col]) = h1;
        }
    } else {
        __nv_bfloat16* base0 = (r0 < 32) ? g_Qb : g_Kb;
        __nv_bfloat16* base1 = (r1 < 32) ? g_Qb : g_Kb;
        int rr0 = (r0 < 32) ? r0 : r0 - 32;
        int rr1 = (r1 < 32) ? r1 : r1 - 32;
        #pragma unroll
        for (int nf = 0; nf < 8; nf++) {
            int col = n0 + wn*64 + nf*8 + 2*lr;
            base0[((size_t)b*TT + col  )*RR + rr0] = __float2bfloat16(acc[nf][0] + bias0);
            base0[((size_t)b*TT + col+1)*RR + rr0] = __float2bfloat16(acc[nf][1] + bias0);
            base1[((size_t)b*TT + col  )*RR + rr1] = __float2bfloat16(acc[nf][2] + bias1);
            base1[((size_t)b*TT + col+1)*RR + rr1] = __float2bfloat16(acc[nf][3] + bias1);
        }
    }
}

// ---------------------------------------------------------------------------
// Kernel 2: flash attention.
//   S phase : warp m16 x n32 (mi=wid>>1, ni=wid&1), Q frags hoisted in regs
//   softmax : registers + 2-warp exchange; per-row alpha/l in smem
//   PV phase: warp m32 x n64 (mi2=wid>>2, ni2=wid&3) -> V ldsm redundancy 2x
// ---------------------------------------------------------------------------
#define QPH 40
#define KPH 40
#define VPH 72
#define PPH 72
#define KBUF (64*KPH)
#define VBUF (CC*VPH)
#define SM_HALVES (64*QPH + 2*KBUF + 2*VBUF + 64*PPH)
#define SM_BYTES  (SM_HALVES*2 + (128 + 128 + 64 + 64)*4)

__global__ __launch_bounds__(256, 2) void attn_kernel(
    const float* __restrict__ x, const float* __restrict__ gamma,
    float* __restrict__ out)
{
    extern __shared__ __align__(16) char smraw[];
    __nv_bfloat16* q_s = (__nv_bfloat16*)smraw;          // [64][40]
    __nv_bfloat16* k_s = q_s + 64*QPH;                   // [2][64][40]
    __nv_bfloat16* v_s = k_s + 2*KBUF;                   // [2][256][72]
    __nv_bfloat16* p_s = v_s + 2*VBUF;                   // [64][72]
    float* ex_max = (float*)(p_s + 64*PPH);              // [8][16]
    float* ex_sum = ex_max + 128;                        // [8][16]
    float* a_s    = ex_sum + 128;                        // [64] per-row alpha
    float* l_s    = a_s + 64;                            // [64] running sum

    const int b    = blockIdx.y;
    const int t0   = blockIdx.x * 64;
    const int tid  = threadIdx.x;
    const int wid  = tid >> 5;
    const int lane = tid & 31;
    const int lq   = lane >> 2, lr = lane & 3;
    const int mi   = wid >> 1,  ni = wid & 1;    // S-phase map
    const int mi2  = wid >> 2,  ni2 = wid & 3;   // PV-phase map (m32 x n64)
    const int l8   = (lane & 7) + ((lane & 8) ? 8 : 0);
    const int lc   = (lane >> 4) * 8;

    // prefetch tile 0
    {
        #pragma unroll
        for (int j = 0; j < 9; j++) {
            int slot = tid + j*256;
            if (slot < 256) {
                int row = slot >> 2, ch = slot & 3;
                cp16(&k_s[row*KPH + ch*8],
                     &g_Kb[((size_t)b*TT + row)*RR + ch*8]);
            } else {
                int vsl = slot - 256;
                int row = vsl >> 3, ch = vsl & 7;
                cp16(&v_s[row*VPH + ch*8],
                     &g_Vb[((size_t)b*CC + row)*TT + ch*8]);
            }
        }
        cpcommit();
    }

    // stage Q, init l
    {
        int row = tid >> 2, ch = tid & 3;
        uint4 qv = *reinterpret_cast<const uint4*>(
            &g_Qb[((size_t)b*TT + t0 + row)*RR + ch*8]);
        *reinterpret_cast<uint4*>(&q_s[row*QPH + ch*8]) = qv;
    }
    if (tid < 64) l_s[tid] = 0.f;
    __syncthreads();
    uint32_t aq[8];
    ldsm4(aq,     &q_s[(mi*16 + l8)*QPH + lc]);
    ldsm4(aq + 4, &q_s[(mi*16 + l8)*QPH + 16 + lc]);

    float acc[2][8][4];
    #pragma unroll
    for (int mg = 0; mg < 2; mg++)
        #pragma unroll
        for (int nf = 0; nf < 8; nf++)
            #pragma unroll
            for (int j = 0; j < 4; j++) acc[mg][nf][j] = 0.f;
    float m_prev[2] = {-1e30f, -1e30f};

    for (int it = 0; it < TT/64; it++) {
        const int buf = it & 1;
        cpwait0();
        __syncthreads();

        if (it + 1 < TT/64) {
            const int s0 = (it+1)*64;
            __nv_bfloat16* kd = k_s + (buf^1)*KBUF;
            __nv_bfloat16* vd = v_s + (buf^1)*VBUF;
            #pragma unroll
            for (int j = 0; j < 9; j++) {
                int slot = tid + j*256;
                if (slot < 256) {
                    int row = slot >> 2, ch = slot & 3;
                    cp16(&kd[row*KPH + ch*8],
                         &g_Kb[((size_t)b*TT + s0 + row)*RR + ch*8]);
                } else {
                    int vsl = slot - 256;
                    int row = vsl >> 3, ch = vsl & 7;
                    cp16(&vd[row*VPH + ch*8],
                         &g_Vb[((size_t)b*CC + row)*TT + s0 + ch*8]);
                }
            }
            cpcommit();
        }

        // ---- S = Q @ K^T : warp m16 x n32 ----
        const __nv_bfloat16* kb = k_s + buf*KBUF;
        float sacc[4][4];
        #pragma unroll
        for (int g = 0; g < 4; g++)
            #pragma unroll
            for (int j = 0; j < 4; j++) sacc[g][j] = 0.f;
        #pragma unroll
        for (int ks = 0; ks < 2; ks++) {
            #pragma unroll
            for (int n2 = 0; n2 < 2; n2++) {
                uint32_t kb4[4];
                ldsm4(kb4, &kb[(ni*32 + n2*16 + l8)*KPH + ks*16 + lc]);
                mmabf(sacc[n2*2+0], aq + ks*4, kb4[0], kb4[2]);
                mmabf(sacc[n2*2+1], aq + ks*4, kb4[1], kb4[3]);
            }
        }

        // ---- online softmax ----
        float mx0 = fmaxf(fmaxf(sacc[0][0], sacc[0][1]), fmaxf(sacc[1][0], sacc[1][1]));
        mx0 = fmaxf(mx0, fmaxf(fmaxf(sacc[2][0], sacc[2][1]), fmaxf(sacc[3][0], sacc[3][1])));
        float mx1 = fmaxf(fmaxf(sacc[0][2], sacc[0][3]), fmaxf(sacc[1][2], sacc[1][3]));
        mx1 = fmaxf(mx1, fmaxf(fmaxf(sacc[2][2], sacc[2][3]), fmaxf(sacc[3][2], sacc[3][3])));
        mx0 = fmaxf(mx0, __shfl_xor_sync(0xffffffffu, mx0, 1));
        mx0 = fmaxf(mx0, __shfl_xor_sync(0xffffffffu, mx0, 2));
        mx1 = fmaxf(mx1, __shfl_xor_sync(0xffffffffu, mx1, 1));
        mx1 = fmaxf(mx1, __shfl_xor_sync(0xffffffffu, mx1, 2));
        if (lr == 0) { ex_max[wid*16 + lq] = mx0; ex_max[wid*16 + 8 + lq] = mx1; }
        __syncthreads();
        mx0 = fmaxf(mx0, ex_max[(wid^1)*16 + lq]);
        mx1 = fmaxf(mx1, ex_max[(wid^1)*16 + 8 + lq]);
        float mn0 = fmaxf(m_prev[0], mx0), mn1 = fmaxf(m_prev[1], mx1);
        float al0 = __expf(m_prev[0] - mn0), al1 = __expf(m_prev[1] - mn1);
        m_prev[0] = mn0; m_prev[1] = mn1;
        if (ni == 0 && lr == 0) {
            a_s[mi*16 + lq]     = al0;      // consumed by PV phase after next sync
            a_s[mi*16 + 8 + lq] = al1;
        }

        float sum0 = 0.f, sum1 = 0.f;
        #pragma unroll
        for (int g = 0; g < 4; g++) {
            sacc[g][0] = __expf(sacc[g][0] - mn0);
            sacc[g][1] = __expf(sacc[g][1] - mn0);
            sacc[g][2] = __expf(sacc[g][2] - mn1);
            sacc[g][3] = __expf(sacc[g][3] - mn1);
            sum0 += sacc[g][0] + sacc[g][1];
            sum1 += sacc[g][2] + sacc[g][3];
        }
        sum0 += __shfl_xor_sync(0xffffffffu, sum0, 1);
        sum0 += __shfl_xor_sync(0xffffffffu, sum0, 2);
        sum1 += __shfl_xor_sync(0xffffffffu, sum1, 1);
        sum1 += __shfl_xor_sync(0xffffffffu, sum1, 2);
        if (lr == 0) { ex_sum[wid*16 + lq] = sum0; ex_sum[wid*16 + 8 + lq] = sum1; }

        // P -> smem (bf16x2)
        #pragma unroll
        for (int g = 0; g < 4; g++) {
            int cb = ni*32 + g*8 + 2*lr;
            __nv_bfloat162 plo = __floats2bfloat162_rn(sacc[g][0], sacc[g][1]);
            __nv_bfloat162 phi = __floats2bfloat162_rn(sacc[g][2], sacc[g][3]);
            *reinterpret_cast<__nv_bfloat162*>(&p_s[(mi*16 + lq)*PPH + cb])     = plo;
            *reinterpret_cast<__nv_bfloat162*>(&p_s[(mi*16 + 8 + lq)*PPH + cb]) = phi;
        }
        __syncthreads();

        // designated lane folds the full row sum into l
        if (ni == 0 && lr == 0) {
            float fs0 = sum0 + ex_sum[(wid^1)*16 + lq];
            float fs1 = sum1 + ex_sum[(wid^1)*16 + 8 + lq];
            l_s[mi*16 + lq]     = l_s[mi*16 + lq]    *al0 + fs0;
            l_s[mi*16 + 8 + lq] = l_s[mi*16 + 8 + lq]*al1 + fs1;
        }

        // ---- O = a*O + P @ V : warp m32 x n64 ----
        float av[2][2];
        av[0][0] = a_s[mi2*32 + lq];      av[0][1] = a_s[mi2*32 + 8 + lq];
        av[1][0] = a_s[mi2*32 + 16 + lq]; av[1][1] = a_s[mi2*32 + 24 + lq];
        #pragma unroll
        for (int mg = 0; mg < 2; mg++)
            #pragma unroll
            for (int nf = 0; nf < 8; nf++) {
                acc[mg][nf][0] *= av[mg][0]; acc[mg][nf][1] *= av[mg][0];
                acc[mg][nf][2] *= av[mg][1]; acc[mg][nf][3] *= av[mg][1];
            }

        const __nv_bfloat16* vb = v_s + buf*VBUF;
        #pragma unroll
        for (int ks = 0; ks < 4; ks++) {
            uint32_t pa[2][4];
            ldsm4(pa[0], &p_s[(mi2*32      + l8)*PPH + ks*16 + lc]);
            ldsm4(pa[1], &p_s[(mi2*32 + 16 + l8)*PPH + ks*16 + lc]);
            #pragma unroll
            for (int cg = 0; cg < 4; cg++) {
                uint32_t vb4[4];
                ldsm4(vb4, &vb[(ni2*64 + cg*16 + l8)*VPH + ks*16 + lc]);
                mmabf(acc[0][cg*2+0], pa[0], vb4[0], vb4[2]);
                mmabf(acc[0][cg*2+1], pa[0], vb4[1], vb4[3]);
                mmabf(acc[1][cg*2+0], pa[1], vb4[0], vb4[2]);
                mmabf(acc[1][cg*2+1], pa[1], vb4[1], vb4[3]);
            }
        }
    }
    __syncthreads();   // l_s final values visible to all

    // ---- epilogue: y[b][c][t] = x + gamma * O/l ----
    const float gm = gamma[0];
    #pragma unroll
    for (int mg = 0; mg < 2; mg++) {
        const int r0   = mi2*32 + mg*16 + lq;
        const float inv0 = 1.0f / l_s[r0];
        const float inv1 = 1.0f / l_s[r0 + 8];
        #pragma unroll
        for (int nf = 0; nf < 8; nf++) {
            int c = ni2*64 + (nf >> 1)*16 + (nf & 1)*8 + 2*lr;
            size_t i0 = ((size_t)(b*CC + c))*TT + t0 + r0;
            out[i0      ] = x[i0      ] + gm*acc[mg][nf][0]*inv0;
            out[i0 + TT ] = x[i0 + TT ] + gm*acc[mg][nf][1]*inv0;
            out[i0 + 8  ] = x[i0 + 8  ] + gm*acc[mg][nf][2]*inv1;
            out[i0+TT+8 ] = x[i0+TT+8 ] + gm*acc[mg][nf][3]*inv1;
        }
    }
}

// ---------------------------------------------------------------------------
extern "C" void kernel_launch(void* const* d_in, const int* in_sizes, int n_in,
                              void* d_out, int out_size) {
    const float* x     = (const float*)d_in[0];
    const float* Wq    = (const float*)d_in[1];
    const float* bq    = (const float*)d_in[2];
    const float* Wk    = (const float*)d_in[3];
    const float* bk    = (const float*)d_in[4];
    const float* Wv    = (const float*)d_in[5];
    const float* bv    = (const float*)d_in[6];
    const float* gamma = (const float*)d_in[7];
    float* out = (float*)d_out;

    (void)in_sizes; (void)n_in; (void)out_size;

    cudaFuncSetAttribute(proj_kernel, cudaFuncAttributeMaxDynamicSharedMemorySize,
                         PROJ_SM_BYTES);
    cudaFuncSetAttribute(attn_kernel, cudaFuncAttributeMaxDynamicSharedMemorySize,
                         SM_BYTES);

    cvt_x_kernel<<<BB*CC*TT/1024, 256>>>(x);
    cvt_w_kernel<<<320*CC/1024, 256>>>(Wq, Wk, Wv);

    dim3 g1(TT/128, 5, BB);
    proj_kernel<<<g1, 256, PROJ_SM_BYTES>>>(bq, bk, bv);

    dim3 g2(TT/64, BB);
    attn_kernel<<<g2, 256, SM_BYTES>>>(x, gamma, out);
}

// round 11
// speedup vs baseline: 1.0496x; 1.0496x over previous
#include <cuda_runtime.h>
#include <cuda_bf16.h>
#include <cstdint>

#define BB 8
#define CC 256
#define TT 2048
#define RR 32

// bf16 scratch
__device__ __nv_bfloat16 g_Qb[BB*TT*RR];    // [b][t][r]
__device__ __nv_bfloat16 g_Kb[BB*TT*RR];    // [b][t][r]
__device__ __nv_bfloat16 g_Vb[BB*CC*TT];    // [b][c][t]
__device__ __nv_bfloat16 g_Xb[BB*CC*TT];    // [b][c][t]
__device__ __nv_bfloat16 g_Wb[320*CC];      // [row][c]  rows: 0-31 q, 32-63 k, 64-319 v

// ---------------------------------------------------------------------------
// PTX helpers
// ---------------------------------------------------------------------------
__device__ __forceinline__ uint32_t smaddr(const void* p) {
    return (uint32_t)__cvta_generic_to_shared(p);
}
__device__ __forceinline__ void cp16(void* dst, const void* src) {
    asm volatile("cp.async.cg.shared.global [%0], [%1], 16;"
                 :: "r"(smaddr(dst)), "l"(src) : "memory");
}
__device__ __forceinline__ void cpcommit() {
    asm volatile("cp.async.commit_group;" ::: "memory");
}
__device__ __forceinline__ void cpwait0() {
    asm volatile("cp.async.wait_group 0;" ::: "memory");
}
__device__ __forceinline__ void barpair(int id) {
    asm volatile("bar.sync %0, 64;" :: "r"(id) : "memory");
}
__device__ __forceinline__ void ldsm4(uint32_t* r, const void* p) {
    asm volatile("ldmatrix.sync.aligned.m8n8.x4.shared.b16 {%0,%1,%2,%3}, [%4];"
        : "=r"(r[0]), "=r"(r[1]), "=r"(r[2]), "=r"(r[3])
        : "r"(smaddr(p)));
}
__device__ __forceinline__ void ldsm4t(uint32_t* r, const void* p) {
    asm volatile("ldmatrix.sync.aligned.m8n8.x4.trans.shared.b16 {%0,%1,%2,%3}, [%4];"
        : "=r"(r[0]), "=r"(r[1]), "=r"(r[2]), "=r"(r[3])
        : "r"(smaddr(p)));
}
__device__ __forceinline__ void mmabf(float* d, const uint32_t* a,
                                      uint32_t b0, uint32_t b1) {
    asm volatile(
        "mma.sync.aligned.m16n8k16.row.col.f32.bf16.bf16.f32 "
        "{%0,%1,%2,%3},{%4,%5,%6,%7},{%8,%9},{%0,%1,%2,%3};"
        : "+f"(d[0]), "+f"(d[1]), "+f"(d[2]), "+f"(d[3])
        : "r"(a[0]), "r"(a[1]), "r"(a[2]), "r"(a[3]), "r"(b0), "r"(b1));
}

// ---------------------------------------------------------------------------
// Prep kernels
// ---------------------------------------------------------------------------
__global__ __launch_bounds__(256) void cvt_x_kernel(const float* __restrict__ x) {
    size_t i = ((size_t)blockIdx.x*256 + threadIdx.x)*4;
    float4 v = *reinterpret_cast<const float4*>(&x[i]);
    __nv_bfloat162 h0 = __floats2bfloat162_rn(v.x, v.y);
    __nv_bfloat162 h1 = __floats2bfloat162_rn(v.z, v.w);
    uint2 pk;
    pk.x = *reinterpret_cast<uint32_t*>(&h0);
    pk.y = *reinterpret_cast<uint32_t*>(&h1);
    *reinterpret_cast<uint2*>(&g_Xb[i]) = pk;
}

__global__ __launch_bounds__(256) void cvt_w_kernel(
    const float* __restrict__ Wq, const float* __restrict__ Wk,
    const float* __restrict__ Wv) {
    int i = (blockIdx.x*256 + threadIdx.x)*4;
    int row = i >> 8, col = i & 255;
    const float* src = (row < 32) ? &Wq[row*CC + col]
                     : (row < 64) ? &Wk[(row-32)*CC + col]
                                  : &Wv[(row-64)*CC + col];
    float4 v = *reinterpret_cast<const float4*>(src);
    __nv_bfloat162 h0 = __floats2bfloat162_rn(v.x, v.y);
    __nv_bfloat162 h1 = __floats2bfloat162_rn(v.z, v.w);
    uint2 pk;
    pk.x = *reinterpret_cast<uint32_t*>(&h0);
    pk.y = *reinterpret_cast<uint32_t*>(&h1);
    *reinterpret_cast<uint2*>(&g_Wb[i]) = pk;
}

// ---------------------------------------------------------------------------
// Kernel 1: projections via bf16 mma (unchanged — fast).
// ---------------------------------------------------------------------------
#define WST 72
#define XST 136
#define WBUF (64*WST)
#define XBUF (64*XST)
#define PROJ_SM_BYTES ((2*WBUF + 2*XBUF)*2)

__global__ __launch_bounds__(256, 2) void proj_kernel(
    const float* __restrict__ bq, const float* __restrict__ bk,
    const float* __restrict__ bv)
{
    extern __shared__ __align__(16) char smraw[];
    __nv_bfloat16* wbuf = (__nv_bfloat16*)smraw;     // [2][64][72]
    __nv_bfloat16* xbuf = wbuf + 2*WBUF;             // [2][64][136]

    const int b    = blockIdx.z;
    const int m0   = blockIdx.y * 64;
    const int n0   = blockIdx.x * 128;
    const int tid  = threadIdx.x;
    const int wid  = tid >> 5;
    const int lane = tid & 31;
    const int lq   = lane >> 2, lr = lane & 3;
    const int wm   = wid >> 1,  wn = wid & 1;
    const int l8   = (lane & 7) + ((lane & 8) ? 8 : 0);
    const int lc   = (lane >> 4) * 8;

    {
        #pragma unroll
        for (int j = 0; j < 2; j++) {
            int slot = tid + j*256;
            int row = slot >> 3, kc = (slot & 7)*8;
            cp16(&wbuf[row*WST + kc], &g_Wb[(m0+row)*CC + kc]);
        }
        #pragma unroll
        for (int j = 0; j < 4; j++) {
            int slot = tid + j*256;
            int row = slot >> 4, tc = (slot & 15)*8;
            cp16(&xbuf[row*XST + tc], &g_Xb[((size_t)b*CC + row)*TT + n0 + tc]);
        }
        cpcommit();
    }

    float acc[8][4];
    #pragma unroll
    for (int nf = 0; nf < 8; nf++)
        #pragma unroll
        for (int j = 0; j < 4; j++) acc[nf][j] = 0.f;

    for (int kc = 0; kc < 4; kc++) {
        const int buf = kc & 1;
        cpwait0();
        __syncthreads();

        if (kc + 1 < 4) {
            const int k0 = (kc+1)*64;
            __nv_bfloat16* wd = wbuf + (buf^1)*WBUF;
            __nv_bfloat16* xd = xbuf + (buf^1)*XBUF;
            #pragma unroll
            for (int j = 0; j < 2; j++) {
                int slot = tid + j*256;
                int row = slot >> 3, kcc = (slot & 7)*8;
                cp16(&wd[row*WST + kcc], &g_Wb[(m0+row)*CC + k0 + kcc]);
            }
            #pragma unroll
            for (int j = 0; j < 4; j++) {
                int slot = tid + j*256;
                int row = slot >> 4, tc = (slot & 15)*8;
                cp16(&xd[row*XST + tc], &g_Xb[((size_t)b*CC + k0 + row)*TT + n0 + tc]);
            }
            cpcommit();
        }

        const __nv_bfloat16* wb = wbuf + buf*WBUF;
        const __nv_bfloat16* xb = xbuf + buf*XBUF;
        #pragma unroll
        for (int ks = 0; ks < 4; ks++) {
            uint32_t a[4];
            ldsm4(a, &wb[(wm*16 + l8)*WST + ks*16 + lc]);
            #pragma unroll
            for (int ng = 0; ng < 4; ng++) {
                uint32_t bx[4];
                ldsm4t(bx, &xb[(ks*16 + l8)*XST + wn*64 + ng*16 + lc]);
                mmabf(acc[ng*2+0], a, bx[0], bx[1]);
                mmabf(acc[ng*2+1], a, bx[2], bx[3]);
            }
        }
        __syncthreads();
    }

    const int r0 = m0 + wm*16 + lq;
    const int r1 = r0 + 8;
    float bias0 = (r0 < 32) ? bq[r0] : (r0 < 64) ? bk[r0-32] : bv[r0-64];
    float bias1 = (r1 < 32) ? bq[r1] : (r1 < 64) ? bk[r1-32] : bv[r1-64];

    if (m0 >= 64) {
        int v0 = r0 - 64, v1 = r1 - 64;
        #pragma unroll
        for (int nf = 0; nf < 8; nf++) {
            int col = n0 + wn*64 + nf*8 + 2*lr;
            __nv_bfloat162 h0 = __floats2bfloat162_rn(acc[nf][0] + bias0,
                                                      acc[nf][1] + bias0);
            __nv_bfloat162 h1 = __floats2bfloat162_rn(acc[nf][2] + bias1,
                                                      acc[nf][3] + bias1);
            *reinterpret_cast<__nv_bfloat162*>(&g_Vb[((size_t)b*CC + v0)*TT + col]) = h0;
            *reinterpret_cast<__nv_bfloat162*>(&g_Vb[((size_t)b*CC + v1)*TT + col]) = h1;
        }
    } else {
        __nv_bfloat16* base0 = (r0 < 32) ? g_Qb : g_Kb;
        __nv_bfloat16* base1 = (r1 < 32) ? g_Qb : g_Kb;
        int rr0 = (r0 < 32) ? r0 : r0 - 32;
        int rr1 = (r1 < 32) ? r1 : r1 - 32;
        #pragma unroll
        for (int nf = 0; nf < 8; nf++) {
            int col = n0 + wn*64 + nf*8 + 2*lr;
            base0[((size_t)b*TT + col  )*RR + rr0] = __float2bfloat16(acc[nf][0] + bias0);
            base0[((size_t)b*TT + col+1)*RR + rr0] = __float2bfloat16(acc[nf][1] + bias0);
            base1[((size_t)b*TT + col  )*RR + rr1] = __float2bfloat16(acc[nf][2] + bias1);
            base1[((size_t)b*TT + col+1)*RR + rr1] = __float2bfloat16(acc[nf][3] + bias1);
        }
    }
}

// ---------------------------------------------------------------------------
// Kernel 2: flash attention — round-6 mapping (S: m16n32, PV: m16n128)
// with pair-local named barriers replacing 2 of 3 CTA-wide syncs per tile.
// Pair (mi) = warps (2mi, 2mi+1): softmax exchange and P hand-off are
// entirely within the pair, so bar.sync(1+mi, 64) suffices.
// ---------------------------------------------------------------------------
#define QPH 40
#define KPH 40
#define VPH 72
#define PPH 72
#define KBUF (64*KPH)
#define VBUF (CC*VPH)
#define SM_HALVES (64*QPH + 2*KBUF + 2*VBUF + 64*PPH)
#define SM_BYTES  (SM_HALVES*2 + 2*128*4)

__global__ __launch_bounds__(256, 2) void attn_kernel(
    const float* __restrict__ x, const float* __restrict__ gamma,
    float* __restrict__ out)
{
    extern __shared__ __align__(16) char smraw[];
    __nv_bfloat16* q_s = (__nv_bfloat16*)smraw;          // [64][40]
    __nv_bfloat16* k_s = q_s + 64*QPH;                   // [2][64][40]
    __nv_bfloat16* v_s = k_s + 2*KBUF;                   // [2][256][72]
    __nv_bfloat16* p_s = v_s + 2*VBUF;                   // [64][72]
    float* ex_max = (float*)(p_s + 64*PPH);              // [8][16]
    float* ex_sum = ex_max + 128;                        // [8][16]

    const int b    = blockIdx.y;
    const int t0   = blockIdx.x * 64;
    const int tid  = threadIdx.x;
    const int wid  = tid >> 5;
    const int lane = tid & 31;
    const int lq   = lane >> 2, lr = lane & 3;
    const int mi   = wid >> 1,  ni = wid & 1;
    const int l8   = (lane & 7) + ((lane & 8) ? 8 : 0);
    const int lc   = (lane >> 4) * 8;
    const int bid  = 1 + mi;                             // named barrier id

    // prefetch tile 0
    {
        #pragma unroll
        for (int j = 0; j < 9; j++) {
            int slot = tid + j*256;
            if (slot < 256) {
                int row = slot >> 2, ch = slot & 3;
                cp16(&k_s[row*KPH + ch*8],
                     &g_Kb[((size_t)b*TT + row)*RR + ch*8]);
            } else {
                int vsl = slot - 256;
                int row = vsl >> 3, ch = vsl & 7;
                cp16(&v_s[row*VPH + ch*8],
                     &g_Vb[((size_t)b*CC + row)*TT + ch*8]);
            }
        }
        cpcommit();
    }

    // stage Q, hoist A fragments
    {
        int row = tid >> 2, ch = tid & 3;
        uint4 qv = *reinterpret_cast<const uint4*>(
            &g_Qb[((size_t)b*TT + t0 + row)*RR + ch*8]);
        *reinterpret_cast<uint4*>(&q_s[row*QPH + ch*8]) = qv;
    }
    __syncthreads();
    uint32_t aq[8];
    ldsm4(aq,     &q_s[(mi*16 + l8)*QPH + lc]);
    ldsm4(aq + 4, &q_s[(mi*16 + l8)*QPH + 16 + lc]);

    float acc[16][4];
    #pragma unroll
    for (int nf = 0; nf < 16; nf++)
        #pragma unroll
        for (int j = 0; j < 4; j++) acc[nf][j] = 0.f;
    float m_prev[2] = {-1e30f, -1e30f};
    float l_run[2]  = {0.f, 0.f};

    for (int it = 0; it < TT/64; it++) {
        const int buf = it & 1;
        cpwait0();
        __syncthreads();                 // single CTA-wide barrier per tile

        if (it + 1 < TT/64) {
            const int s0 = (it+1)*64;
            __nv_bfloat16* kd = k_s + (buf^1)*KBUF;
            __nv_bfloat16* vd = v_s + (buf^1)*VBUF;
            #pragma unroll
            for (int j = 0; j < 9; j++) {
                int slot = tid + j*256;
                if (slot < 256) {
                    int row = slot >> 2, ch = slot & 3;
                    cp16(&kd[row*KPH + ch*8],
                         &g_Kb[((size_t)b*TT + s0 + row)*RR + ch*8]);
                } else {
                    int vsl = slot - 256;
                    int row = vsl >> 3, ch = vsl & 7;
                    cp16(&vd[row*VPH + ch*8],
                         &g_Vb[((size_t)b*CC + row)*TT + s0 + ch*8]);
                }
            }
            cpcommit();
        }

        // ---- S = Q @ K^T : warp m16 x n32 ----
        const __nv_bfloat16* kb = k_s + buf*KBUF;
        float sacc[4][4];
        #pragma unroll
        for (int g = 0; g < 4; g++)
            #pragma unroll
            for (int j = 0; j < 4; j++) sacc[g][j] = 0.f;
        #pragma unroll
        for (int ks = 0; ks < 2; ks++) {
            #pragma unroll
            for (int n2 = 0; n2 < 2; n2++) {
                uint32_t kb4[4];
                ldsm4(kb4, &kb[(ni*32 + n2*16 + l8)*KPH + ks*16 + lc]);
                mmabf(sacc[n2*2+0], aq + ks*4, kb4[0], kb4[2]);
                mmabf(sacc[n2*2+1], aq + ks*4, kb4[1], kb4[3]);
            }
        }

        // ---- online softmax (pair-local exchange) ----
        float mx0 = fmaxf(fmaxf(sacc[0][0], sacc[0][1]), fmaxf(sacc[1][0], sacc[1][1]));
        mx0 = fmaxf(mx0, fmaxf(fmaxf(sacc[2][0], sacc[2][1]), fmaxf(sacc[3][0], sacc[3][1])));
        float mx1 = fmaxf(fmaxf(sacc[0][2], sacc[0][3]), fmaxf(sacc[1][2], sacc[1][3]));
        mx1 = fmaxf(mx1, fmaxf(fmaxf(sacc[2][2], sacc[2][3]), fmaxf(sacc[3][2], sacc[3][3])));
        mx0 = fmaxf(mx0, __shfl_xor_sync(0xffffffffu, mx0, 1));
        mx0 = fmaxf(mx0, __shfl_xor_sync(0xffffffffu, mx0, 2));
        mx1 = fmaxf(mx1, __shfl_xor_sync(0xffffffffu, mx1, 1));
        mx1 = fmaxf(mx1, __shfl_xor_sync(0xffffffffu, mx1, 2));
        if (lr == 0) { ex_max[wid*16 + lq] = mx0; ex_max[wid*16 + 8 + lq] = mx1; }
        barpair(bid);
        mx0 = fmaxf(mx0, ex_max[(wid^1)*16 + lq]);
        mx1 = fmaxf(mx1, ex_max[(wid^1)*16 + 8 + lq]);
        float mn0 = fmaxf(m_prev[0], mx0), mn1 = fmaxf(m_prev[1], mx1);
        float al0 = __expf(m_prev[0] - mn0), al1 = __expf(m_prev[1] - mn1);
        m_prev[0] = mn0; m_prev[1] = mn1;

        float sum0 = 0.f, sum1 = 0.f;
        #pragma unroll
        for (int g = 0; g < 4; g++) {
            sacc[g][0] = __expf(sacc[g][0] - mn0);
            sacc[g][1] = __expf(sacc[g][1] - mn0);
            sacc[g][2] = __expf(sacc[g][2] - mn1);
            sacc[g][3] = __expf(sacc[g][3] - mn1);
            sum0 += sacc[g][0] + sacc[g][1];
            sum1 += sacc[g][2] + sacc[g][3];
        }
        sum0 += __shfl_xor_sync(0xffffffffu, sum0, 1);
        sum0 += __shfl_xor_sync(0xffffffffu, sum0, 2);
        sum1 += __shfl_xor_sync(0xffffffffu, sum1, 1);
        sum1 += __shfl_xor_sync(0xffffffffu, sum1, 2);
        if (lr == 0) { ex_sum[wid*16 + lq] = sum0; ex_sum[wid*16 + 8 + lq] = sum1; }

        // P -> smem (bf16x2, pair-local consumption)
        #pragma unroll
        for (int g = 0; g < 4; g++) {
            int cb = ni*32 + g*8 + 2*lr;
            __nv_bfloat162 plo = __floats2bfloat162_rn(sacc[g][0], sacc[g][1]);
            __nv_bfloat162 phi = __floats2bfloat162_rn(sacc[g][2], sacc[g][3]);
            *reinterpret_cast<__nv_bfloat162*>(&p_s[(mi*16 + lq)*PPH + cb])     = plo;
            *reinterpret_cast<__nv_bfloat162*>(&p_s[(mi*16 + 8 + lq)*PPH + cb]) = phi;
        }
        // rescale accumulators while P store drains
        #pragma unroll
        for (int nf = 0; nf < 16; nf++) {
            acc[nf][0] *= al0; acc[nf][1] *= al0;
            acc[nf][2] *= al1; acc[nf][3] *= al1;
        }
        barpair(bid);
        l_run[0] = l_run[0]*al0 + sum0 + ex_sum[(wid^1)*16 + lq];
        l_run[1] = l_run[1]*al1 + sum1 + ex_sum[(wid^1)*16 + 8 + lq];

        // ---- O += P @ V : warp m16 x n128 ----
        const __nv_bfloat16* vb = v_s + buf*VBUF;
        #pragma unroll
        for (int ks = 0; ks < 4; ks++) {
            uint32_t pa[4];
            ldsm4(pa, &p_s[(mi*16 + l8)*PPH + ks*16 + lc]);
            #pragma unroll
            for (int cg = 0; cg < 8; cg++) {
                uint32_t vb4[4];
                ldsm4(vb4, &vb[(ni*128 + cg*16 + l8)*VPH + ks*16 + lc]);
                mmabf(acc[cg*2+0], pa, vb4[0], vb4[2]);
                mmabf(acc[cg*2+1], pa, vb4[1], vb4[3]);
            }
        }
    }

    // ---- epilogue: y[b][c][t] = x + gamma * O/l ----
    const float gm   = gamma[0];
    const float inv0 = 1.0f / l_run[0];
    const float inv1 = 1.0f / l_run[1];
    const int   trow = t0 + mi*16 + lq;
    #pragma unroll
    for (int nf = 0; nf < 16; nf++) {
        int c = ni*128 + (nf >> 1)*16 + (nf & 1)*8 + 2*lr;
        size_t i0 = ((size_t)(b*CC + c))*TT + trow;
        out[i0      ] = x[i0      ] + gm*acc[nf][0]*inv0;
        out[i0 + TT ] = x[i0 + TT ] + gm*acc[nf][1]*inv0;
        out[i0 + 8  ] = x[i0 + 8  ] + gm*acc[nf][2]*inv1;
        out[i0+TT+8 ] = x[i0+TT+8 ] + gm*acc[nf][3]*inv1;
    }
}

// ---------------------------------------------------------------------------
extern "C" void kernel_launch(void* const* d_in, const int* in_sizes, int n_in,
                              void* d_out, int out_size) {
    const float* x     = (const float*)d_in[0];
    const float* Wq    = (const float*)d_in[1];
    const float* bq    = (const float*)d_in[2];
    const float* Wk    = (const float*)d_in[3];
    const float* bk    = (const float*)d_in[4];
    const float* Wv    = (const float*)d_in[5];
    const float* bv    = (const float*)d_in[6];
    const float* gamma = (const float*)d_in[7];
    float* out = (float*)d_out;

    (void)in_sizes; (void)n_in; (void)out_size;

    cudaFuncSetAttribute(proj_kernel, cudaFuncAttributeMaxDynamicSharedMemorySize,
                         PROJ_SM_BYTES);
    cudaFuncSetAttribute(attn_kernel, cudaFuncAttributeMaxDynamicSharedMemorySize,
                         SM_BYTES);

    cvt_x_kernel<<<BB*CC*TT/1024, 256>>>(x);
    cvt_w_kernel<<<320*CC/1024, 256>>>(Wq, Wk, Wv);

    dim3 g1(TT/128, 5, BB);
    proj_kernel<<<g1, 256, PROJ_SM_BYTES>>>(bq, bk, bv);

    dim3 g2(TT/64, BB);
    attn_kernel<<<g2, 256, SM_BYTES>>>(x, gamma, out);
}